// round 4
// baseline (speedup 1.0000x reference)
#include <cuda_runtime.h>
#include <math.h>

typedef unsigned long long ull;

#define DT_STEP 0.1f
#define EPS_TAU 1e-6f

constexpr int B = 256, T = 512, I = 64, H = 512, O = 64;
constexpr int GRID = 144;   // 128 layer CTAs + 16 out-proj CTAs, all co-resident
constexpr int KA = H + I;   // 576  layer-0 fused K
constexpr int KB = 2 * H;   // 1024 layer-1 fused K
constexpr int ADS = 66;     // duplicated-activation row stride (floats): even, not mult of 4

constexpr int SMEM_FLOATS = KA * 32 + KB * 32 + 2 * 32 * ADS + 128;
constexpr int SMEM_BYTES = SMEM_FLOATS * 4;  // ~217 KB

__device__ float g_h0[2][B * H];
__device__ float g_h1[2][B * H];
__device__ unsigned g_arrive;
__device__ volatile unsigned g_release;

__global__ void k_init() {
    int idx = blockIdx.x * blockDim.x + threadIdx.x;
    if (idx < B * H) {
        g_h0[0][idx] = 0.0f;
        g_h1[0][idx] = 0.0f;
    }
    if (idx == 0) {
        g_arrive = 0;
        g_release = 0;
    }
}

// packed fp32x2 FMA: d.xy += a.xy * b.xy   (sm_103a FFMA2, PTX-only)
__device__ __forceinline__ void ffma2(ull& d, ull a, ull b) {
    asm("fma.rn.f32x2 %0, %1, %2, %0;" : "+l"(d) : "l"(a), "l"(b));
}
__device__ __forceinline__ void upk(float& x, float& y, ull v) {
    asm("mov.b64 {%0,%1}, %2;" : "=f"(x), "=f"(y) : "l"(v));
}

// Grid barrier: ticket arrive + monotone epoch release. __threadfence() (gpu
// scope) orders traffic and invalidates L1D so cross-CTA hidden state is fresh.
__device__ __forceinline__ void gsync(unsigned& epoch) {
    epoch++;
    __syncthreads();
    __threadfence();
    if (threadIdx.x == 0) {
        unsigned ticket = atomicAdd(&g_arrive, 1u) + 1u;
        if (ticket == (unsigned)GRID * epoch) {
            g_release = epoch;
        } else {
            while (g_release < epoch) {
            }
        }
    }
    __syncthreads();
    __threadfence();
}

// One K-segment of the 32x32-tile GEMM: acc += act(32 x K) * Wseg^T.
// Weights smem-resident [k][32]. Activations streamed from global,
// double-buffered, stored DUPLICATED ((a,a) pairs) so both FFMA2 operands are
// direct ld.shared.b64 -- zero pack movs. Thread owns (row=lane, 4 cols).
__device__ __forceinline__ void gemm_seg(ull acc[2],
                                         const float* __restrict__ src,
                                         int rowStride, int kTiles,
                                         const float* __restrict__ wseg,
                                         float* __restrict__ actd, int& buf) {
    const int tid = threadIdx.x;
    const int lr = tid >> 3;         // staging row 0..31
    const int lc4 = (tid & 7) << 2;  // staging k offset
    const int r = tid & 31;          // compute row (= lane)
    const int c0 = (tid >> 5) << 2;  // compute col group (uniform per warp)

    float4 v = *reinterpret_cast<const float4*>(src + lr * rowStride + lc4);
    for (int kt = 0; kt < kTiles; kt++) {
        float* sd = actd + (buf & 1) * (32 * ADS) + lr * ADS;
#pragma unroll
        for (int i = 0; i < 4; i++) {
            float f = (i == 0) ? v.x : (i == 1) ? v.y : (i == 2) ? v.z : v.w;
            *reinterpret_cast<float2*>(sd + 2 * (lc4 + i)) = make_float2(f, f);
        }
        __syncthreads();
        if (kt + 1 < kTiles)
            v = *reinterpret_cast<const float4*>(src + lr * rowStride +
                                                 (kt + 1) * 32 + lc4);
        const float* ad = actd + (buf & 1) * (32 * ADS) + r * ADS;
        const float* wk = wseg + kt * (32 * 32) + c0;
#pragma unroll
        for (int kp = 0; kp < 16; kp++) {
            ull a0 = *reinterpret_cast<const ull*>(ad + 4 * kp);       // (a_k,a_k)
            ull a1 = *reinterpret_cast<const ull*>(ad + 4 * kp + 2);   // (a_k1,a_k1)
            ull w00 = *reinterpret_cast<const ull*>(wk + (2 * kp) * 32);
            ull w01 = *reinterpret_cast<const ull*>(wk + (2 * kp) * 32 + 2);
            ull w10 = *reinterpret_cast<const ull*>(wk + (2 * kp + 1) * 32);
            ull w11 = *reinterpret_cast<const ull*>(wk + (2 * kp + 1) * 32 + 2);
            ffma2(acc[0], a0, w00);
            ffma2(acc[1], a0, w01);
            ffma2(acc[0], a1, w10);
            ffma2(acc[1], a1, w11);
        }
        buf ^= 1;
    }
}

// Persistent kernel: whole T=512 scan, weights staged to smem once.
// Per step t:
//   phase A: CTAs 0..127  -> h0 Euler update (K=576); CTAs 128..143 -> y(t-1)
//   [grid barrier]
//   phase B: CTAs 0..127  -> h1 Euler update (K=1024, drive+recurrent fused)
//   [grid barrier]
__global__ __launch_bounds__(256, 1) void k_scan(
    const float* __restrict__ x, const float* __restrict__ Win0,
    const float* __restrict__ bin0, const float* __restrict__ A0,
    const float* __restrict__ tau0, const float* __restrict__ Win1,
    const float* __restrict__ bin1, const float* __restrict__ A1,
    const float* __restrict__ tau1, const float* __restrict__ Wout,
    const float* __restrict__ bout, float* __restrict__ out) {
    extern __shared__ float smem[];
    float* wA = smem;                   // [KA][32]  (out-CTAs: Wout [H][32])
    float* wB = smem + KA * 32;         // [KB][32]
    float* actd = wB + KB * 32;         // [2][32][ADS] duplicated activations
    float* misc = actd + 2 * 32 * ADS;  // biases / inv-tau for this col tile

    const int tid = threadIdx.x;
    const int bx = blockIdx.x;
    const int r = tid & 31;
    const int c0 = (tid >> 5) << 2;
    const bool is_main = (bx < 128);
    int row0, col0;
    if (is_main) {
        row0 = (bx >> 4) * 32;
        col0 = (bx & 15) * 32;
    } else {
        int idx = bx - 128;
        row0 = (idx >> 1) * 32;
        col0 = (idx & 1) * 32;
    }

    // ---- one-time weight staging into smem ([k][col] layout) ----
    if (is_main) {
        for (int i = tid; i < H * 32; i += 256) {
            int c = i >> 9, k = i & (H - 1);
            wA[k * 32 + c] = A0[(col0 + c) * H + k];
            wB[k * 32 + c] = Win1[(col0 + c) * H + k];
            wB[(H + k) * 32 + c] = A1[(col0 + c) * H + k];
        }
        for (int i = tid; i < I * 32; i += 256) {
            int c = i >> 6, k = i & (I - 1);
            wA[(H + k) * 32 + c] = Win0[(col0 + c) * I + k];
        }
        if (tid < 32) {
            misc[tid] = bin0[col0 + tid];
            misc[32 + tid] = 1.0f / (fabsf(tau0[col0 + tid]) + EPS_TAU);
            misc[64 + tid] = bin1[col0 + tid];
            misc[96 + tid] = 1.0f / (fabsf(tau1[col0 + tid]) + EPS_TAU);
        }
    } else {
        for (int i = tid; i < H * 32; i += 256) {
            int c = i >> 9, k = i & (H - 1);
            wA[k * 32 + c] = Wout[(col0 + c) * H + k];
        }
        if (tid < 32) misc[tid] = bout[col0 + tid];
    }
    __syncthreads();

    unsigned epoch = 0;
    int buf = 0;

    for (int t = 0; t < T; t++) {
        const int pr = t & 1;
        const int pw = pr ^ 1;

        // ---------------- phase A ----------------
        if (is_main) {
            const float* h0r = g_h0[pr];
            ull acc[2] = {0ull, 0ull};
            gemm_seg(acc, h0r + row0 * H, H, H / 32, wA, actd, buf);
            gemm_seg(acc, x + row0 * (T * I) + t * I, T * I, I / 32,
                     wA + H * 32, actd, buf);
            float s01x, s01y, s23x, s23y;
            upk(s01x, s01y, acc[0]);
            upk(s23x, s23y, acc[1]);
            float sv[4] = {s01x, s01y, s23x, s23y};
            const int gb = row0 + r;
            const float* hrow = h0r + gb * H + col0;
            float* wrow = g_h0[pw] + gb * H + col0;
#pragma unroll
            for (int j = 0; j < 4; j++) {
                int c = c0 + j;
                float s = sv[j] + misc[c];
                float hp = hrow[c];
                wrow[c] = hp + DT_STEP * misc[32 + c] * (tanhf(s) - hp);
            }
        } else if (t > 0) {
            ull acc[2] = {0ull, 0ull};
            gemm_seg(acc, g_h1[pr] + row0 * H, H, H / 32, wA, actd, buf);
            float s01x, s01y, s23x, s23y;
            upk(s01x, s01y, acc[0]);
            upk(s23x, s23y, acc[1]);
            float sv[4] = {s01x, s01y, s23x, s23y};
            const int gb = row0 + r;
#pragma unroll
            for (int j = 0; j < 4; j++) {
                out[gb * (T * O) + (t - 1) * O + col0 + c0 + j] =
                    sv[j] + misc[c0 + j];
            }
        }
        gsync(epoch);

        // ---------------- phase B ----------------
        if (is_main) {
            const float* h1r = g_h1[pr];
            ull acc[2] = {0ull, 0ull};
            gemm_seg(acc, g_h0[pw] + row0 * H, H, H / 32, wB, actd, buf);
            gemm_seg(acc, h1r + row0 * H, H, H / 32, wB + H * 32, actd, buf);
            float s01x, s01y, s23x, s23y;
            upk(s01x, s01y, acc[0]);
            upk(s23x, s23y, acc[1]);
            float sv[4] = {s01x, s01y, s23x, s23y};
            const int gb = row0 + r;
            const float* hrow = h1r + gb * H + col0;
            float* wrow = g_h1[pw] + gb * H + col0;
#pragma unroll
            for (int j = 0; j < 4; j++) {
                int c = c0 + j;
                float s = sv[j] + misc[64 + c];
                float hp = hrow[c];
                wrow[c] = hp + DT_STEP * misc[96 + c] * (tanhf(s) - hp);
            }
        }
        gsync(epoch);
    }

    // ---------------- epilogue: y(T-1); final h1 lives in buf 0 ----------------
    if (!is_main) {
        ull acc[2] = {0ull, 0ull};
        gemm_seg(acc, g_h1[0] + row0 * H, H, H / 32, wA, actd, buf);
        float s01x, s01y, s23x, s23y;
        upk(s01x, s01y, acc[0]);
        upk(s23x, s23y, acc[1]);
        float sv[4] = {s01x, s01y, s23x, s23y};
        const int gb = row0 + r;
#pragma unroll
        for (int j = 0; j < 4; j++) {
            out[gb * (T * O) + (T - 1) * O + col0 + c0 + j] =
                sv[j] + misc[c0 + j];
        }
    }
}

extern "C" void kernel_launch(void* const* d_in, const int* in_sizes, int n_in,
                              void* d_out, int out_size) {
    const float* x    = (const float*)d_in[0];
    const float* Win0 = (const float*)d_in[1];
    const float* bin0 = (const float*)d_in[2];
    const float* A0   = (const float*)d_in[3];
    const float* tau0 = (const float*)d_in[4];
    const float* Win1 = (const float*)d_in[5];
    const float* bin1 = (const float*)d_in[6];
    const float* A1   = (const float*)d_in[7];
    const float* tau1 = (const float*)d_in[8];
    const float* Wout = (const float*)d_in[9];
    const float* bout = (const float*)d_in[10];
    float* out = (float*)d_out;

    cudaFuncSetAttribute(k_scan, cudaFuncAttributeMaxDynamicSharedMemorySize,
                         SMEM_BYTES);

    k_init<<<(B * H + 255) / 256, 256>>>();
    k_scan<<<GRID, 256, SMEM_BYTES>>>(x, Win0, bin0, A0, tau0, Win1, bin1, A1,
                                      tau1, Wout, bout, out);
}

// round 6
// speedup vs baseline: 2.3043x; 2.3043x over previous
#include <cuda_runtime.h>
#include <cuda_bf16.h>
#include <math.h>
#include <stdint.h>

#define DT_STEP 0.1f
#define EPS_TAU 1e-6f

constexpr int B = 256, T = 512, I = 64, H = 512, O = 64;
constexpr int GRID = 144;  // 128 layer CTAs + 16 out-proj CTAs; all co-resident

// smem offsets in b32 units
constexpr int WA_HI = 0;              // phase-A weight frags hi (9216 pairs)
constexpr int WA_LO = 9216;
constexpr int WB_HI = 18432;          // phase-B weight frags (16384 pairs)
constexpr int WB_LO = 34816;
constexpr int ACT = 51200;            // 2 bufs x (1024 hi + 1024 lo)
constexpr int MISC = ACT + 4096;      // 128 floats: bias/itau per col tile
constexpr int SMEM_B32 = MISC + 128;
constexpr int SMEM_BYTES = SMEM_B32 * 4;  // 221,696 B

__device__ float g_h0[2][B * H];
__device__ float g_h1[2][B * H];
__device__ unsigned g_arrive;
__device__ volatile unsigned g_release;

__global__ void k_init() {
    int idx = blockIdx.x * blockDim.x + threadIdx.x;
    if (idx < B * H) {
        g_h0[0][idx] = 0.0f; g_h0[1][idx] = 0.0f;
        g_h1[0][idx] = 0.0f; g_h1[1][idx] = 0.0f;
    }
    if (idx == 0) { g_arrive = 0; g_release = 0; }
}

// pack two fp32 -> bf16x2 (elem0 = e0 in low half)
__device__ __forceinline__ uint32_t pack2(float e0, float e1) {
    uint32_t r;
    asm("cvt.rn.bf16x2.f32 %0, %1, %2;" : "=r"(r) : "f"(e1), "f"(e0));
    return r;
}
__device__ __forceinline__ float bfr(float x) {
    return __bfloat162float(__float2bfloat16_rn(x));
}

// m16n8k16 row.col f32.bf16.bf16.f32 (sm_80+, available on plain sm_103)
__device__ __forceinline__ void mmaw(float* d, uint4 a, uint2 b) {
    asm volatile(
        "mma.sync.aligned.m16n8k16.row.col.f32.bf16.bf16.f32 "
        "{%0,%1,%2,%3},{%4,%5,%6,%7},{%8,%9},{%0,%1,%2,%3};"
        : "+f"(d[0]), "+f"(d[1]), "+f"(d[2]), "+f"(d[3])
        : "r"(a.x), "r"(a.y), "r"(a.z), "r"(a.w), "r"(b.x), "r"(b.y));
}

// Grid barrier: ticket arrive + monotone epoch release; __threadfence() (gpu
// scope) orders traffic and invalidates L1D so cross-CTA state is fresh.
__device__ __forceinline__ void gsync(unsigned& epoch) {
    epoch++;
    __syncthreads();
    __threadfence();
    if (threadIdx.x == 0) {
        unsigned ticket = atomicAdd(&g_arrive, 1u) + 1u;
        if (ticket == (unsigned)GRID * epoch) g_release = epoch;
        else while (g_release < epoch) {}
    }
    __syncthreads();
    __threadfence();
}

// One-time weight staging into FRAGMENT ORDER:
// pair idx -> {s=idx&1, lane=(idx>>1)&31, nb=(idx>>6)&3, ktG=idx>>8}
// value = (W[n][k], W[n][k+1]), n = nb*8 + (lane>>2), k = ktG*16 + (lane&3)*2 + s*8
// k >= klim reads from (W1, s1) with k-klim.
__device__ void stage_wfrag(uint32_t* sm32, int hiOff, int loOff, int pairs,
                            const float* W0, int s0, int klim,
                            const float* W1, int s1) {
    for (int idx = threadIdx.x; idx < pairs; idx += 256) {
        int s = idx & 1, lane = (idx >> 1) & 31;
        int nb = (idx >> 6) & 3, ktG = idx >> 8;
        int gid = lane >> 2, tig = lane & 3;
        int n = nb * 8 + gid, k = ktG * 16 + tig * 2 + s * 8;
        const float* src; int kk;
        if (k < klim) { src = W0 + n * s0; kk = k; }
        else { src = W1 + n * s1; kk = k - klim; }
        float w0 = src[kk], w1 = src[kk + 1];
        float h0 = bfr(w0), h1 = bfr(w1);
        sm32[hiOff + idx] = pack2(h0, h1);
        sm32[loOff + idx] = pack2(w0 - h0, w1 - h1);
    }
}

// One GEMM phase for this CTA's 32x32 tile: acc += act(32 x 64*nch) * W^T.
// Chunks [0,nchA) stream from srcA (stride stA), rest from srcB (stride stB).
// Activations converted fp32 -> bf16 hi/lo and stored in fragment order,
// double-buffered, one __syncthreads per chunk. Weight frags smem-resident.
__device__ __forceinline__ void gemm_phase(float* acc, uint32_t* sm,
                                           const uint32_t* whi, const uint32_t* wlo,
                                           const float* srcA, int stA, int nchA,
                                           const float* srcB, int stB, int nch,
                                           int rb, int nb, int lane) {
    const int tid = threadIdx.x;
    const int kts = tid >> 6, rbs = (tid >> 5) & 1, lanes = tid & 31;
    const int gids = lanes >> 2, tigs = lanes & 3;
    const int sdst = ((kts * 2 + rbs) * 32 + lanes) * 4;
    float2 v0, v1, v2, v3;

    auto LD = [&](int c) {
        const float* s; int ko, st;
        if (c < nchA) { s = srcA; st = stA; ko = c * 64; }
        else { s = srcB; st = stB; ko = (c - nchA) * 64; }
        const float* p = s + (rbs * 16 + gids) * st + ko + kts * 16 + tigs * 2;
        v0 = *(const float2*)p;            // (row g,   k)
        v1 = *(const float2*)(p + 8);      // (row g,   k+8)
        v2 = *(const float2*)(p + 8 * st); // (row g+8, k)
        v3 = *(const float2*)(p + 8 * st + 8);
    };
    auto ST = [&](int c) {
        uint32_t* hb = sm + ACT + (c & 1) * 2048 + sdst;
        float h00 = bfr(v0.x), h01 = bfr(v0.y), h10 = bfr(v2.x), h11 = bfr(v2.y);
        float h20 = bfr(v1.x), h21 = bfr(v1.y), h30 = bfr(v3.x), h31 = bfr(v3.y);
        *(uint4*)hb = make_uint4(pack2(h00, h01), pack2(h10, h11),
                                 pack2(h20, h21), pack2(h30, h31));
        *(uint4*)(hb + 1024) =
            make_uint4(pack2(v0.x - h00, v0.y - h01), pack2(v2.x - h10, v2.y - h11),
                       pack2(v1.x - h20, v1.y - h21), pack2(v3.x - h30, v3.y - h31));
    };

    LD(0); ST(0);
    for (int c = 0; c < nch; c++) {
        __syncthreads();
        bool more = (c + 1 < nch);
        if (more) LD(c + 1);
        const uint32_t* ab = sm + ACT + (c & 1) * 2048;
#pragma unroll
        for (int kt = 0; kt < 4; kt++) {
            int ktG = c * 4 + kt;
            uint4 ah = *(const uint4*)(ab + ((kt * 2 + rb) * 32 + lane) * 4);
            uint4 al = *(const uint4*)(ab + 1024 + ((kt * 2 + rb) * 32 + lane) * 4);
            uint2 bh = *(const uint2*)(whi + ((ktG * 4 + nb) * 32 + lane) * 2);
            uint2 bl = *(const uint2*)(wlo + ((ktG * 4 + nb) * 32 + lane) * 2);
            mmaw(acc, ah, bh);
            mmaw(acc, ah, bl);
            mmaw(acc, al, bh);
        }
        if (more) ST(c + 1);
    }
    __syncthreads();
}

__global__ __launch_bounds__(256, 1) void k_scan(
    const float* __restrict__ x, const float* __restrict__ Win0,
    const float* __restrict__ bin0, const float* __restrict__ A0,
    const float* __restrict__ tau0, const float* __restrict__ Win1,
    const float* __restrict__ bin1, const float* __restrict__ A1,
    const float* __restrict__ tau1, const float* __restrict__ Wout,
    const float* __restrict__ bout, float* __restrict__ out) {
    extern __shared__ uint32_t sm[];
    float* miscf = (float*)(sm + MISC);
    const int tid = threadIdx.x, bx = blockIdx.x;
    const int w = tid >> 5, lane = tid & 31;
    const int gid = lane >> 2, tig = lane & 3;
    const int rb = w & 1, nb = w >> 1;  // warp tile: rows rb*16, cols nb*8
    const bool is_main = (bx < 128);
    int row0, col0;
    if (is_main) { row0 = (bx >> 4) * 32; col0 = (bx & 15) * 32; }
    else { int idx = bx - 128; row0 = (idx >> 1) * 32; col0 = (idx & 1) * 32; }

    // ---- one-time weight staging (bf16 hi/lo, fragment order) ----
    if (is_main) {
        stage_wfrag(sm, WA_HI, WA_LO, 9216, A0 + col0 * H, H, 512,
                    Win0 + col0 * I, I);
        stage_wfrag(sm, WB_HI, WB_LO, 16384, Win1 + col0 * H, H, 512,
                    A1 + col0 * H, H);
        if (tid < 32) {
            miscf[tid] = bin0[col0 + tid];
            miscf[32 + tid] = 1.0f / (fabsf(tau0[col0 + tid]) + EPS_TAU);
            miscf[64 + tid] = bin1[col0 + tid];
            miscf[96 + tid] = 1.0f / (fabsf(tau1[col0 + tid]) + EPS_TAU);
        }
    } else {
        stage_wfrag(sm, 0, 8192, 8192, Wout + col0 * H, H, 1 << 20, Wout, H);
        if (tid < 32) miscf[tid] = bout[col0 + tid];
    }
    __syncthreads();

    const int gr = row0 + rb * 16 + gid;      // D-frag rows gr, gr+8
    const int gc = col0 + nb * 8 + tig * 2;   // D-frag cols gc, gc+1
    const int ci = nb * 8 + tig * 2;
    unsigned epoch = 0;

    for (int t = 0; t < T; t++) {
        const int pr = t & 1, pw = pr ^ 1;

        // ---------------- phase A ----------------
        if (is_main) {
            const float* h0r = g_h0[pr];
            float acc[4] = {0.f, 0.f, 0.f, 0.f};
            gemm_phase(acc, sm, sm + WA_HI, sm + WA_LO,
                       h0r + row0 * H, H, 8,
                       x + row0 * (T * I) + t * I, T * I, 9, rb, nb, lane);
            float b0v = miscf[ci], b1v = miscf[ci + 1];
            float i0 = miscf[32 + ci], i1 = miscf[32 + ci + 1];
            float2 hpa = *(const float2*)(h0r + gr * H + gc);
            float2 hpb = *(const float2*)(h0r + (gr + 8) * H + gc);
            float2 o0, o1;
            o0.x = hpa.x + DT_STEP * i0 * (tanhf(acc[0] + b0v) - hpa.x);
            o0.y = hpa.y + DT_STEP * i1 * (tanhf(acc[1] + b1v) - hpa.y);
            o1.x = hpb.x + DT_STEP * i0 * (tanhf(acc[2] + b0v) - hpb.x);
            o1.y = hpb.y + DT_STEP * i1 * (tanhf(acc[3] + b1v) - hpb.y);
            *(float2*)(g_h0[pw] + gr * H + gc) = o0;
            *(float2*)(g_h0[pw] + (gr + 8) * H + gc) = o1;
        } else if (t > 0) {
            const float* h1r = g_h1[pr];  // h1 of step t-1
            float acc[4] = {0.f, 0.f, 0.f, 0.f};
            gemm_phase(acc, sm, sm + 0, sm + 8192,
                       h1r + row0 * H, H, 8, h1r, H, 8, rb, nb, lane);
            float b0v = miscf[ci], b1v = miscf[ci + 1];
            *(float2*)(out + gr * (T * O) + (t - 1) * O + gc) =
                make_float2(acc[0] + b0v, acc[1] + b1v);
            *(float2*)(out + (gr + 8) * (T * O) + (t - 1) * O + gc) =
                make_float2(acc[2] + b0v, acc[3] + b1v);
        }
        gsync(epoch);

        // ---------------- phase B ----------------
        if (is_main) {
            const float* h1r = g_h1[pr];
            float acc[4] = {0.f, 0.f, 0.f, 0.f};
            gemm_phase(acc, sm, sm + WB_HI, sm + WB_LO,
                       g_h0[pw] + row0 * H, H, 8,
                       h1r + row0 * H, H, 16, rb, nb, lane);
            float b0v = miscf[64 + ci], b1v = miscf[64 + ci + 1];
            float i0 = miscf[96 + ci], i1 = miscf[96 + ci + 1];
            float2 hpa = *(const float2*)(h1r + gr * H + gc);
            float2 hpb = *(const float2*)(h1r + (gr + 8) * H + gc);
            float2 o0, o1;
            o0.x = hpa.x + DT_STEP * i0 * (tanhf(acc[0] + b0v) - hpa.x);
            o0.y = hpa.y + DT_STEP * i1 * (tanhf(acc[1] + b1v) - hpa.y);
            o1.x = hpb.x + DT_STEP * i0 * (tanhf(acc[2] + b0v) - hpb.x);
            o1.y = hpb.y + DT_STEP * i1 * (tanhf(acc[3] + b1v) - hpb.y);
            *(float2*)(g_h1[pw] + gr * H + gc) = o0;
            *(float2*)(g_h1[pw] + (gr + 8) * H + gc) = o1;
        }
        gsync(epoch);
    }

    // ---- epilogue: y(T-1); final h1 lives in buf 0 ----
    if (!is_main) {
        const float* h1r = g_h1[0];
        float acc[4] = {0.f, 0.f, 0.f, 0.f};
        gemm_phase(acc, sm, sm + 0, sm + 8192,
                   h1r + row0 * H, H, 8, h1r, H, 8, rb, nb, lane);
        float b0v = miscf[ci], b1v = miscf[ci + 1];
        *(float2*)(out + gr * (T * O) + (T - 1) * O + gc) =
            make_float2(acc[0] + b0v, acc[1] + b1v);
        *(float2*)(out + (gr + 8) * (T * O) + (T - 1) * O + gc) =
            make_float2(acc[2] + b0v, acc[3] + b1v);
    }
}

extern "C" void kernel_launch(void* const* d_in, const int* in_sizes, int n_in,
                              void* d_out, int out_size) {
    const float* x    = (const float*)d_in[0];
    const float* Win0 = (const float*)d_in[1];
    const float* bin0 = (const float*)d_in[2];
    const float* A0   = (const float*)d_in[3];
    const float* tau0 = (const float*)d_in[4];
    const float* Win1 = (const float*)d_in[5];
    const float* bin1 = (const float*)d_in[6];
    const float* A1   = (const float*)d_in[7];
    const float* tau1 = (const float*)d_in[8];
    const float* Wout = (const float*)d_in[9];
    const float* bout = (const float*)d_in[10];
    float* out = (float*)d_out;

    cudaFuncSetAttribute(k_scan, cudaFuncAttributeMaxDynamicSharedMemorySize,
                         SMEM_BYTES);

    k_init<<<(B * H + 255) / 256, 256>>>();
    k_scan<<<GRID, 256, SMEM_BYTES>>>(x, Win0, bin0, A0, tau0, Win1, bin1, A1,
                                      tau1, Wout, bout, out);
}